// round 6
// baseline (speedup 1.0000x reference)
#include <cuda_runtime.h>
#include <cstdint>

#define N_NODES 1000000
__device__ float g_rowsum[N_NODES];

// Detect whether edge_index is truly int64 or was demoted to int32 by JAX.
// int64 indices are < 1e6 -> high 32 bits of every 8-byte word are zero.
__device__ __forceinline__ bool detect_i64(const void* idx) {
    const unsigned long long* p = (const unsigned long long*)idx;
    return ((p[0] | p[1] | p[2] | p[3]) >> 32) == 0ULL;
}

__device__ __forceinline__ float et_of(float x) {
    float lr = x > 0.0f ? x : 0.01f * x;
    return __expf(lr);
}

__device__ __forceinline__ void load_rows8(const void* idx, int i0, bool i64, int r[8]) {
    if (i64) {
        const longlong2* q = (const longlong2*)idx + (i0 >> 1);
        longlong2 v0 = __ldcs(q + 0);
        longlong2 v1 = __ldcs(q + 1);
        longlong2 v2 = __ldcs(q + 2);
        longlong2 v3 = __ldcs(q + 3);
        r[0] = (int)v0.x; r[1] = (int)v0.y;
        r[2] = (int)v1.x; r[3] = (int)v1.y;
        r[4] = (int)v2.x; r[5] = (int)v2.y;
        r[6] = (int)v3.x; r[7] = (int)v3.y;
    } else {
        const int4* q = (const int4*)((const int*)idx + i0);
        int4 v0 = __ldcs(q + 0);
        int4 v1 = __ldcs(q + 1);
        r[0] = v0.x; r[1] = v0.y; r[2] = v0.z; r[3] = v0.w;
        r[4] = v1.x; r[5] = v1.y; r[6] = v1.z; r[7] = v1.w;
    }
}

__global__ void __launch_bounds__(256) accum_kernel(const void* __restrict__ idx,
                                                    const float* __restrict__ attr, int E) {
    int t = blockIdx.x * blockDim.x + threadIdx.x;
    int i0 = t * 8;
    if (i0 >= E) return;
    bool i64 = detect_i64(idx);

    if (i0 + 7 < E) {
        int r[8];
        load_rows8(idx, i0, i64, r);
        float4 a0 = __ldcs((const float4*)(attr + i0) + 0);
        float4 a1 = __ldcs((const float4*)(attr + i0) + 1);
        float e[8] = { et_of(a0.x), et_of(a0.y), et_of(a0.z), et_of(a0.w),
                       et_of(a1.x), et_of(a1.y), et_of(a1.z), et_of(a1.w) };
        #pragma unroll
        for (int j = 0; j < 8; j++)
            atomicAdd(&g_rowsum[r[j]], e[j]);
    } else {
        for (int i = i0; i < E; i++) {
            int r = i64 ? (int)((const long long*)idx)[i] : ((const int*)idx)[i];
            atomicAdd(&g_rowsum[r], et_of(attr[i]));
        }
    }
}

__global__ void __launch_bounds__(256) recip_kernel() {
    int i = blockIdx.x * blockDim.x + threadIdx.x;  // one float4 per thread
    float4* p = (float4*)g_rowsum;
    if (i < N_NODES / 4) {
        float4 v = p[i];
        v.x = 1.0f / v.x; v.y = 1.0f / v.y; v.z = 1.0f / v.z; v.w = 1.0f / v.w;
        p[i] = v;
    }
}

__global__ void __launch_bounds__(256) norm_kernel(const void* __restrict__ idx,
                                                   const float* __restrict__ attr,
                                                   float* __restrict__ out, int E) {
    int t = blockIdx.x * blockDim.x + threadIdx.x;
    int i0 = t * 8;
    if (i0 >= E) return;
    bool i64 = detect_i64(idx);

    if (i0 + 7 < E) {
        int r[8];
        load_rows8(idx, i0, i64, r);
        // Issue all 8 gathers back-to-back (deep MLP in the L1tex queue).
        float n[8];
        #pragma unroll
        for (int j = 0; j < 8; j++)
            n[j] = g_rowsum[r[j]];
        float4 a0 = __ldcs((const float4*)(attr + i0) + 0);
        float4 a1 = __ldcs((const float4*)(attr + i0) + 1);
        float4 o0, o1;
        o0.x = et_of(a0.x) * n[0];
        o0.y = et_of(a0.y) * n[1];
        o0.z = et_of(a0.z) * n[2];
        o0.w = et_of(a0.w) * n[3];
        o1.x = et_of(a1.x) * n[4];
        o1.y = et_of(a1.y) * n[5];
        o1.z = et_of(a1.z) * n[6];
        o1.w = et_of(a1.w) * n[7];
        __stcs((float4*)(out + i0) + 0, o0);
        __stcs((float4*)(out + i0) + 1, o1);
    } else {
        for (int i = i0; i < E; i++) {
            int r = i64 ? (int)((const long long*)idx)[i] : ((const int*)idx)[i];
            out[i] = et_of(attr[i]) * g_rowsum[r];
        }
    }
}

extern "C" void kernel_launch(void* const* d_in, const int* in_sizes, int n_in,
                              void* d_out, int out_size) {
    const void*  edge_index = d_in[0];               // [2, E] (row = first E entries)
    const float* edge_attr  = (const float*)d_in[1]; // [E]
    float*       out        = (float*)d_out;
    int E = in_sizes[1];

    void* rowsum_ptr = nullptr;
    cudaGetSymbolAddress(&rowsum_ptr, g_rowsum);
    cudaMemsetAsync(rowsum_ptr, 0, N_NODES * sizeof(float));

    const int T = 256;
    int eblocks = ((E + 7) / 8 + T - 1) / T;
    int rblocks = (N_NODES / 4 + T - 1) / T;

    accum_kernel<<<eblocks, T>>>(edge_index, edge_attr, E);
    recip_kernel<<<rblocks, T>>>();
    norm_kernel<<<eblocks, T>>>(edge_index, edge_attr, out, E);
}